// round 15
// baseline (speedup 1.0000x reference)
#include <cuda_runtime.h>
#include <cuda_bf16.h>
#include <cuda_fp16.h>

// Problem constants (fixed by dataset)
#define BB 2
#define CC 256
#define HH 56
#define WW 56
#define NN 64
#define MM 8
#define PP 7
#define R_PER_IMG (NN + NN*MM)        // 576
#define R_TOTAL   (BB * R_PER_IMG)    // 1152
#define MAXK 12
#define KCAP 10                       // true max support count

#define FS      71                    // fm smem row stride in uint2 (4ch fp16)
#define FROWB   (FS * 8)              // row stride in bytes
#define TROWS   66                    // tmp rows

// Per-roi tables.
// g_meta[r*16 + row], rows 0..6 = y (p), 7..13 = x (q). meta = off | (cnt<<8)
// g_yinfo[r] = ylo | (span4<<8)
// g_kmax[r*2 + a] = warp-uniform EXACT max cnt for axis a (1..10)
// g_wgth[(r*14+row)*12 + k] = broadcast half2 (w,w), zero-padded to 12
__device__ int      g_meta[R_TOTAL * 16];
__device__ int      g_yinfo[R_TOTAL];
__device__ int      g_kmax[R_TOTAL * 2];
__device__ __align__(16) unsigned g_wgth[R_TOTAL * 14 * MAXK];

// ---------------------------------------------------------------------------
// Kernel A: build sparse interpolation tables. Reference math exactly
// (fp32 accumulation of weights; final store rounded to broadcast half2).
// ---------------------------------------------------------------------------
__global__ void prep_kernel(const float* __restrict__ boxes,
                            const float* __restrict__ gts) {
    int t = blockIdx.x * blockDim.x + threadIdx.x;
    if (t >= R_TOTAL * 2) return;
    int r = t >> 1, a = t & 1;
    int b = r / R_PER_IMG, idx = r % R_PER_IMG;

    float x1, y1, x2, y2;
    if (idx < NN) {
        const float* bx = boxes + (b * NN + idx) * 4;
        x1 = bx[0]; y1 = bx[1]; x2 = bx[2]; y2 = bx[3];
    } else {
        int n = (idx - NN) >> 3, m = (idx - NN) & 7;
        const float* bx = boxes + (b * NN + n) * 4;
        const float* gx = gts   + (b * MM + m) * 4;
        x1 = fminf(bx[0], gx[0]); y1 = fminf(bx[1], gx[1]);
        x2 = fmaxf(bx[2], gx[2]); y2 = fmaxf(bx[3], gx[3]);
    }

    float start = a ? x1 : y1;
    float len   = fmaxf(a ? (x2 - x1) : (y2 - y1), 1.0f);
    const float dimf = 56.0f;
    const int   dim  = 56;

    float bin = len / 7.0f;
    int   g   = (int)ceilf(bin);
    float gf  = (float)g;
    float inv = 1.0f / gf;

    int lo_min = 1 << 20, hi_max = -1, cnt_max = 1;
    for (int p = 0; p < 7; p++) {
        float acc[MAXK];
        #pragma unroll
        for (int k = 0; k < MAXK; k++) acc[k] = 0.0f;
        int base = -1, hi = -1;
        float c0 = start + (float)p * bin;
        for (int s = 0; s < 8; s++) {
            if (s >= g) break;
            float coord = c0 + ((float)s + 0.5f) * bin / gf;
            if (!(coord >= -1.0f && coord <= dimf)) continue;
            float c = fmaxf(coord, 0.0f);
            int low = (int)floorf(c);
            int high; float cv;
            if (low >= dim - 1) { low = dim - 1; high = dim - 1; cv = (float)low; }
            else                { high = low + 1; cv = c; }
            float l  = cv - (float)low;
            float wl = (1.0f - l) * inv;
            float wh = l * inv;
            if (base < 0) base = low;
            int d  = low  - base;
            int d2 = high - base;
            if (d  >= 0 && d  < MAXK) acc[d]  += wl;
            if (d2 >= 0 && d2 < MAXK) acc[d2] += wh;
            if (high > hi) hi = high;
        }
        int cnt = (base < 0) ? 0 : (hi - base + 1);
        if (base < 0) base = 0;
        if (cnt > KCAP) cnt = KCAP;
        if (base < lo_min) lo_min = base;
        if (base + cnt > hi_max) hi_max = base + cnt;
        if (cnt > cnt_max) cnt_max = cnt;
        g_meta[r * 16 + a * 7 + p] = base | (cnt << 8);
        unsigned* wp = g_wgth + (size_t)((r * 14 + a * 7 + p)) * MAXK;
        #pragma unroll
        for (int k = 0; k < MAXK; k++) {
            unsigned hb = __half_as_ushort(__float2half_rn(acc[k]));
            wp[k] = hb * 0x10001u;        // broadcast half2 (w, w)
        }
    }
    if (cnt_max < 1)    cnt_max = 1;
    if (cnt_max > KCAP) cnt_max = KCAP;
    g_kmax[r * 2 + a] = cnt_max;
    if (a == 0) {
        int lo = lo_min, span = hi_max - lo_min;
        if (span < 1) { lo = 0; span = 1; }
        int span4 = (span + 3) & ~3;
        g_yinfo[r] = lo | (span4 << 8);
    }
}

// ---------------------------------------------------------------------------
// Helpers
// ---------------------------------------------------------------------------
__device__ __forceinline__ __half2 u2h(unsigned u) {
    return *reinterpret_cast<__half2*>(&u);
}
__device__ __forceinline__ unsigned h2u(__half2 h) {
    return *reinterpret_cast<unsigned*>(&h);
}
__device__ __forceinline__ unsigned ucomp(uint4 v, int i) {
    return i == 0 ? v.x : i == 1 ? v.y : i == 2 ? v.z : v.w;
}
__device__ __forceinline__ uint2 pack4h(float a, float b, float c, float d) {
    __half2 h01 = __floats2half2_rn(a, b);
    __half2 h23 = __floats2half2_rn(c, d);
    uint2 r;
    r.x = h2u(h01);
    r.y = h2u(h23);
    return r;
}

#define BARPAIR(idp) asm volatile("bar.sync %0, 64;" :: "r"(idp) : "memory")

// ---------------------------------------------------------------------------
// Stage bodies. Masking entirely via zero-padded fp16 WEIGHTS over zeroed /
// finite pad data -> plain LDS with immediate offsets, no selects.
// Within-roi accumulation in half2 (HFMA2). KM = exact warp-uniform max cnt.
// Stage-1: warp pair alternates hb groups (side*4, step 8) into shared tmp.
// ---------------------------------------------------------------------------
template<int KM>
__device__ __forceinline__ void s1loop(const char* fmb, uint2* tmpw,
        int ylo, int span4, int hsub, int qx, bool act1, int side,
        int offu, const unsigned* wph) {
    const uint4* w4 = (const uint4*)wph;
    uint4 wa = __ldg(w4);
    uint4 wb = (KM > 4) ? __ldg(w4 + 1) : make_uint4(0u, 0u, 0u, 0u);
    uint4 wc = (KM > 8) ? __ldg(w4 + 2) : make_uint4(0u, 0u, 0u, 0u);
    #pragma unroll 1
    for (int hb = side * 4; hb < span4; hb += 8) {
        if (act1) {
            int h = hb + hsub;
            const uint2* row = (const uint2*)(fmb + (ylo + h) * FROWB) + offu;
            __half2 a01 = u2h(0u), a23 = u2h(0u);
            #pragma unroll
            for (int k = 0; k < KM; k++) {
                unsigned wk = (k < 4) ? ucomp(wa, k)
                             : (k < 8) ? ucomp(wb, k - 4) : ucomp(wc, k - 8);
                uint2 hv = row[k];
                a01 = __hfma2(u2h(wk), u2h(hv.x), a01);
                a23 = __hfma2(u2h(wk), u2h(hv.y), a23);
            }
            tmpw[h * 7 + qx] = make_uint2(h2u(a01), h2u(a23));
        }
    }
}

template<int KM>
__device__ __forceinline__ void s2cell(const char* tb, int basei,
        const unsigned* wph, float2& s01, float2& s23) {
    const uint4* w4 = (const uint4*)wph;
    uint4 ua = __ldg(w4);
    uint4 ub = (KM > 4) ? __ldg(w4 + 1) : make_uint4(0u, 0u, 0u, 0u);
    uint4 uc = (KM > 8) ? __ldg(w4 + 2) : make_uint4(0u, 0u, 0u, 0u);
    __half2 h01 = u2h(0u), h23 = u2h(0u);
    #pragma unroll
    for (int k = 0; k < KM; k++) {
        unsigned wk = (k < 4) ? ucomp(ua, k)
                     : (k < 8) ? ucomp(ub, k - 4) : ucomp(uc, k - 8);
        uint2 tv = *(const uint2*)(tb + (basei + k * 7) * 8);
        h01 = __hfma2(u2h(wk), u2h(tv.x), h01);
        h23 = __hfma2(u2h(wk), u2h(tv.y), h23);
    }
    s01 = __half22float2(h01);
    s23 = __half22float2(h23);
}

// ---------------------------------------------------------------------------
// Kernel B: one CTA per (channel-quad, image, n-quarter). 8 warps in 4 pairs;
// each pair owns one n and a SHARED tmp buffer. Stage-1 h-groups alternate
// between the pair's warps; stage-2 splits the 49 cells (25/24). Named
// barrier (64 threads) separates the phases. smem 49KB -> 4 CTAs/SM.
// ---------------------------------------------------------------------------
__global__ void __launch_bounds__(256, 4)
roi_main_kernel(const float* __restrict__ fm, float* __restrict__ out) {
    const int cq = blockIdx.x;               // channel quad: c0 = 4*cq
    const int b  = blockIdx.y;
    const int nbase = blockIdx.z * 4;        // 4 n per CTA, one per warp pair

    __shared__ uint2 fm_s[60 * FS];          // 34080 B
    __shared__ uint2 tmp_s[4][TROWS * 7];    // 14784 B  (shared per warp pair)

    const int tid = threadIdx.x;
    const int c0 = cq * 4;

    // ---- stage fm[b][c0..c0+3] packed fp16; zero ALL pad regions + tmp ----
    {
        const uint2 z2 = make_uint2(0u, 0u);
        for (int i = tid; i < 4 * FS; i += 256) fm_s[56 * FS + i] = z2;   // rows 56..59
        for (int i = tid; i < 56 * 15; i += 256) {                        // cols 56..70
            int h = i / 15, w = 56 + (i % 15);
            fm_s[h * FS + w] = z2;
        }
        uint2* tz = &tmp_s[0][0];
        for (int i = tid; i < 4 * TROWS * 7; i += 256) tz[i] = z2;        // tmp finite

        const float4* s0 = (const float4*)(fm + ((size_t)(b * CC + c0)     ) * (HH * WW));
        const float4* s1 = (const float4*)(fm + ((size_t)(b * CC + c0 + 1)) * (HH * WW));
        const float4* s2 = (const float4*)(fm + ((size_t)(b * CC + c0 + 2)) * (HH * WW));
        const float4* s3 = (const float4*)(fm + ((size_t)(b * CC + c0 + 3)) * (HH * WW));
        for (int i = tid; i < 784; i += 256) {
            float4 v0 = s0[i];
            float4 v1 = s1[i];
            float4 v2 = s2[i];
            float4 v3 = s3[i];
            int h = i / 14, w = (i % 14) * 4;
            uint2* d = &fm_s[h * FS + w];
            d[0] = pack4h(v0.x, v1.x, v2.x, v3.x);
            d[1] = pack4h(v0.y, v1.y, v2.y, v3.y);
            d[2] = pack4h(v0.z, v1.z, v2.z, v3.z);
            d[3] = pack4h(v0.w, v1.w, v2.w, v3.w);
        }
    }
    __syncthreads();

    const int wid  = tid >> 5;
    const int lane = tid & 31;
    const int pairIdx = wid >> 1;            // 0..3
    const int side    = wid & 1;             // 0 or 1 within the pair
    const int barid   = 1 + pairIdx;         // named barrier id (1..4)
    uint2* tmpw = tmp_s[pairIdx];
    const char* tb  = (const char*)tmpw;
    const char* fmb = (const char*)fm_s;

    // stage-1 lane mapping: lanes 0..27 -> (hsub, qx)
    const int qx   = lane % 7;
    const int hsub = lane / 7;
    const bool act1 = (lane < 28);

    // stage-2 cell mapping: side 0 -> cells 0..24, side 1 -> cells 25..48
    const int cell = side ? (25 + lane) : lane;
    const bool actc = lane < (side ? 24 : 25);
    const int p0 = cell / 7, q0 = cell % 7;
    const int p0s = actc ? p0 : 0;           // safe index for inactive lanes

    const int n = nbase + pairIdx;

    float4 acc0 = make_float4(0.f, 0.f, 0.f, 0.f);

    #pragma unroll 1
    for (int j = 0; j < 9; j++) {
        const int r = b * R_PER_IMG + ((j == 0) ? n : (NN + n * 8 + (j - 1)));
        const float wroi = (j == 0) ? 1.0f : 0.125f;
        const int yinfo = __ldg(&g_yinfo[r]);
        const int ylo   = yinfo & 0xFF;
        const int span4 = yinfo >> 8;
        const int ky    = __ldg(&g_kmax[r * 2]);
        const int kx    = __ldg(&g_kmax[r * 2 + 1]);
        const int mbase = r * 16;
        const unsigned* whbase = g_wgth + (size_t)r * 168;

        // ---- stage 1: x-interp into shared tmp (alternating h-groups) ----
        {
            int metax = __ldg(&g_meta[mbase + 7 + qx]);
            int offx = metax & 0xFF;
            const unsigned* wpx = whbase + (7 + qx) * 12;
            #define CS1(K) case K: s1loop<K>(fmb, tmpw, ylo, span4, hsub, qx, act1, side, offx, wpx); break;
            switch (kx) {
                CS1(1) CS1(2) CS1(3) CS1(4) CS1(5)
                CS1(6) CS1(7) CS1(8) CS1(9)
                default: s1loop<10>(fmb, tmpw, ylo, span4, hsub, qx, act1, side, offx, wpx); break;
            }
            #undef CS1
        }
        BARPAIR(barid);     // pair: tmp fully written

        // ---- stage 2: y-interp from tmp (one cell per lane) ----
        {
            int meta0 = __ldg(&g_meta[mbase + p0s]);
            int base0 = ((meta0 & 0xFF) - ylo) * 7 + q0;
            if (!actc) base0 = 0;            // safe read, result discarded
            const unsigned* wp0 = whbase + p0s * 12;

            float2 s001, s023;
            #define CS2(K) case K: s2cell<K>(tb, base0, wp0, s001, s023); break;
            switch (ky) {
                CS2(1) CS2(2) CS2(3) CS2(4) CS2(5)
                CS2(6) CS2(7) CS2(8) CS2(9)
                default: s2cell<10>(tb, base0, wp0, s001, s023); break;
            }
            #undef CS2
            acc0.x += wroi * s001.x; acc0.y += wroi * s001.y;
            acc0.z += wroi * s023.x; acc0.w += wroi * s023.y;
        }
        BARPAIR(barid);     // pair: tmp consumed, safe to overwrite
    }

    // ---- store out[b][n][c][p][q], channels c0..c0+3, this lane's cell ----
    if (actc) {
        float* o = out + ((size_t)(b * NN + n) * CC + c0) * (PP * PP);
        o[cell]       = acc0.x;
        o[49 + cell]  = acc0.y;
        o[98 + cell]  = acc0.z;
        o[147 + cell] = acc0.w;
    }
}

// ---------------------------------------------------------------------------
extern "C" void kernel_launch(void* const* d_in, const int* in_sizes, int n_in,
                              void* d_out, int out_size) {
    const float* fm    = (const float*)d_in[0];
    const float* boxes = (const float*)d_in[1];
    const float* gts   = (const float*)d_in[2];
    float* out = (float*)d_out;

    prep_kernel<<<(R_TOTAL * 2 + 127) / 128, 128>>>(boxes, gts);

    dim3 grid(CC / 4, BB, 16);
    roi_main_kernel<<<grid, 256>>>(fm, out);
}

// round 16
// speedup vs baseline: 1.1193x; 1.1193x over previous
#include <cuda_runtime.h>
#include <cuda_bf16.h>
#include <cuda_fp16.h>

// Problem constants (fixed by dataset)
#define BB 2
#define CC 256
#define HH 56
#define WW 56
#define NN 64
#define MM 8
#define PP 7
#define R_PER_IMG (NN + NN*MM)        // 576
#define R_TOTAL   (BB * R_PER_IMG)    // 1152
#define MAXK 12
#define KCAP 10                       // true max support count

#define FS      68                    // fm smem row stride in uint2 (4ch fp16)
#define FROWB   (FS * 8)              // row stride in bytes (544)
#define FROWS   59                    // fm rows (ylo + span4 - 1 <= 58)
#define TROWS   56                    // tmp rows (writes bounded by 56)
#define TCLAMP  (55 * 7 + 6)          // max valid tmp cell index (391)

// Per-roi tables.
// g_meta[r*16 + row], rows 0..6 = y (p), 7..13 = x (q). meta = off | (cnt<<8)
// g_yinfo[r] = ylo | (span4<<8)
// g_kmax[r*2 + a] = warp-uniform EXACT max cnt for axis a (1..10)
// g_wgth[(r*14+row)*12 + k] = broadcast half2 (w,w), zero-padded to 12
__device__ int      g_meta[R_TOTAL * 16];
__device__ int      g_yinfo[R_TOTAL];
__device__ int      g_kmax[R_TOTAL * 2];
__device__ __align__(16) unsigned g_wgth[R_TOTAL * 14 * MAXK];

// ---------------------------------------------------------------------------
// Kernel A: build sparse interpolation tables. Reference math exactly
// (fp32 accumulation of weights; final store rounded to broadcast half2).
// ---------------------------------------------------------------------------
__global__ void prep_kernel(const float* __restrict__ boxes,
                            const float* __restrict__ gts) {
    int t = blockIdx.x * blockDim.x + threadIdx.x;
    if (t >= R_TOTAL * 2) return;
    int r = t >> 1, a = t & 1;
    int b = r / R_PER_IMG, idx = r % R_PER_IMG;

    float x1, y1, x2, y2;
    if (idx < NN) {
        const float* bx = boxes + (b * NN + idx) * 4;
        x1 = bx[0]; y1 = bx[1]; x2 = bx[2]; y2 = bx[3];
    } else {
        int n = (idx - NN) >> 3, m = (idx - NN) & 7;
        const float* bx = boxes + (b * NN + n) * 4;
        const float* gx = gts   + (b * MM + m) * 4;
        x1 = fminf(bx[0], gx[0]); y1 = fminf(bx[1], gx[1]);
        x2 = fmaxf(bx[2], gx[2]); y2 = fmaxf(bx[3], gx[3]);
    }

    float start = a ? x1 : y1;
    float len   = fmaxf(a ? (x2 - x1) : (y2 - y1), 1.0f);
    const float dimf = 56.0f;
    const int   dim  = 56;

    float bin = len / 7.0f;
    int   g   = (int)ceilf(bin);
    float gf  = (float)g;
    float inv = 1.0f / gf;

    int lo_min = 1 << 20, hi_max = -1, cnt_max = 1;
    for (int p = 0; p < 7; p++) {
        float acc[MAXK];
        #pragma unroll
        for (int k = 0; k < MAXK; k++) acc[k] = 0.0f;
        int base = -1, hi = -1;
        float c0 = start + (float)p * bin;
        for (int s = 0; s < 8; s++) {
            if (s >= g) break;
            float coord = c0 + ((float)s + 0.5f) * bin / gf;
            if (!(coord >= -1.0f && coord <= dimf)) continue;
            float c = fmaxf(coord, 0.0f);
            int low = (int)floorf(c);
            int high; float cv;
            if (low >= dim - 1) { low = dim - 1; high = dim - 1; cv = (float)low; }
            else                { high = low + 1; cv = c; }
            float l  = cv - (float)low;
            float wl = (1.0f - l) * inv;
            float wh = l * inv;
            if (base < 0) base = low;
            int d  = low  - base;
            int d2 = high - base;
            if (d  >= 0 && d  < MAXK) acc[d]  += wl;
            if (d2 >= 0 && d2 < MAXK) acc[d2] += wh;
            if (high > hi) hi = high;
        }
        int cnt = (base < 0) ? 0 : (hi - base + 1);
        if (base < 0) base = 0;
        if (cnt > KCAP) cnt = KCAP;
        if (base < lo_min) lo_min = base;
        if (base + cnt > hi_max) hi_max = base + cnt;
        if (cnt > cnt_max) cnt_max = cnt;
        g_meta[r * 16 + a * 7 + p] = base | (cnt << 8);
        unsigned* wp = g_wgth + (size_t)((r * 14 + a * 7 + p)) * MAXK;
        #pragma unroll
        for (int k = 0; k < MAXK; k++) {
            unsigned hb = __half_as_ushort(__float2half_rn(acc[k]));
            wp[k] = hb * 0x10001u;        // broadcast half2 (w, w)
        }
    }
    if (cnt_max < 1)    cnt_max = 1;
    if (cnt_max > KCAP) cnt_max = KCAP;
    g_kmax[r * 2 + a] = cnt_max;
    if (a == 0) {
        int lo = lo_min, span = hi_max - lo_min;
        if (span < 1) { lo = 0; span = 1; }
        int span4 = (span + 3) & ~3;
        g_yinfo[r] = lo | (span4 << 8);
    }
}

// ---------------------------------------------------------------------------
// Helpers
// ---------------------------------------------------------------------------
__device__ __forceinline__ __half2 u2h(unsigned u) {
    return *reinterpret_cast<__half2*>(&u);
}
__device__ __forceinline__ unsigned h2u(__half2 h) {
    return *reinterpret_cast<unsigned*>(&h);
}
__device__ __forceinline__ unsigned ucomp(uint4 v, int i) {
    return i == 0 ? v.x : i == 1 ? v.y : i == 2 ? v.z : v.w;
}
__device__ __forceinline__ uint2 pack4h(float a, float b, float c, float d) {
    __half2 h01 = __floats2half2_rn(a, b);
    __half2 h23 = __floats2half2_rn(c, d);
    uint2 r;
    r.x = h2u(h01);
    r.y = h2u(h23);
    return r;
}

// ---------------------------------------------------------------------------
// Stage bodies. Masking entirely via zero-padded fp16 WEIGHTS over zeroed /
// finite pad data -> plain LDS with immediate offsets, no selects.
// Within-roi accumulation in half2 (HFMA2). KM = exact warp-uniform max cnt.
// Stage-2 clamps the tap index into the finite tmp region; only zero-weight
// taps ever clamp (real taps satisfy (span-1)*7+q <= TCLAMP).
// ---------------------------------------------------------------------------
template<int KM>
__device__ __forceinline__ void s1loop(const char* fmb, uint2* tmpw,
        int ylo, int span4, int hsub, int qx, bool act1,
        int offu, const unsigned* wph) {
    const uint4* w4 = (const uint4*)wph;
    uint4 wa = __ldg(w4);
    uint4 wb = (KM > 4) ? __ldg(w4 + 1) : make_uint4(0u, 0u, 0u, 0u);
    uint4 wc = (KM > 8) ? __ldg(w4 + 2) : make_uint4(0u, 0u, 0u, 0u);
    #pragma unroll 2
    for (int hb = 0; hb < span4; hb += 4) {
        if (act1) {
            int h = hb + hsub;
            const uint2* row = (const uint2*)(fmb + (ylo + h) * FROWB) + offu;
            __half2 a01 = u2h(0u), a23 = u2h(0u);
            #pragma unroll
            for (int k = 0; k < KM; k++) {
                unsigned wk = (k < 4) ? ucomp(wa, k)
                             : (k < 8) ? ucomp(wb, k - 4) : ucomp(wc, k - 8);
                uint2 hv = row[k];
                a01 = __hfma2(u2h(wk), u2h(hv.x), a01);
                a23 = __hfma2(u2h(wk), u2h(hv.y), a23);
            }
            tmpw[h * 7 + qx] = make_uint2(h2u(a01), h2u(a23));
        }
    }
}

template<int KM>
__device__ __forceinline__ void s2cell(const char* tb, int basei,
        const unsigned* wph, float2& s01, float2& s23) {
    const uint4* w4 = (const uint4*)wph;
    uint4 ua = __ldg(w4);
    uint4 ub = (KM > 4) ? __ldg(w4 + 1) : make_uint4(0u, 0u, 0u, 0u);
    uint4 uc = (KM > 8) ? __ldg(w4 + 2) : make_uint4(0u, 0u, 0u, 0u);
    __half2 h01 = u2h(0u), h23 = u2h(0u);
    #pragma unroll
    for (int k = 0; k < KM; k++) {
        unsigned wk = (k < 4) ? ucomp(ua, k)
                     : (k < 8) ? ucomp(ub, k - 4) : ucomp(uc, k - 8);
        int ai = basei + k * 7;
        if (ai > TCLAMP) ai = TCLAMP;     // zero-weight taps only
        uint2 tv = *(const uint2*)(tb + ai * 8);
        h01 = __hfma2(u2h(wk), u2h(tv.x), h01);
        h23 = __hfma2(u2h(wk), u2h(tv.y), h23);
    }
    s01 = __half22float2(h01);
    s23 = __half22float2(h23);
}

// ---------------------------------------------------------------------------
// Kernel B: one CTA per (channel-quad, image, n-eighth). fm 4ch fp16 packed
// in smem (59 rows x 68 stride, pads zeroed); tmp fp16 (56 rows), zero-init.
// 8 warps, one n each; per n: box roi + 8 ctx rois; roi-level accum fp32.
// smem 55.9KB + regs<=64  ->  4 CTAs/SM (32 warps) for latency hiding.
// ---------------------------------------------------------------------------
__global__ void __launch_bounds__(256, 4)
roi_main_kernel(const float* __restrict__ fm, float* __restrict__ out) {
    const int cq = blockIdx.x;               // channel quad: c0 = 4*cq
    const int b  = blockIdx.y;
    const int nbase = blockIdx.z * 8;        // 8 n per CTA, one per warp

    __shared__ uint2 fm_s[FROWS * FS];       // 32096 B
    __shared__ uint2 tmp_s[8][TROWS * 7];    // 25088 B

    const int tid = threadIdx.x;
    const int c0 = cq * 4;

    // ---- stage fm[b][c0..c0+3] packed fp16; zero ALL pad regions + tmp ----
    {
        const uint2 z2 = make_uint2(0u, 0u);
        for (int i = tid; i < 3 * FS; i += 256) fm_s[56 * FS + i] = z2;   // rows 56..58
        for (int i = tid; i < 56 * 12; i += 256) {                        // cols 56..67
            int h = i / 12, w = 56 + (i % 12);
            fm_s[h * FS + w] = z2;
        }
        uint2* tz = &tmp_s[0][0];
        for (int i = tid; i < 8 * TROWS * 7; i += 256) tz[i] = z2;        // tmp finite

        const float4* s0 = (const float4*)(fm + ((size_t)(b * CC + c0)     ) * (HH * WW));
        const float4* s1 = (const float4*)(fm + ((size_t)(b * CC + c0 + 1)) * (HH * WW));
        const float4* s2 = (const float4*)(fm + ((size_t)(b * CC + c0 + 2)) * (HH * WW));
        const float4* s3 = (const float4*)(fm + ((size_t)(b * CC + c0 + 3)) * (HH * WW));
        for (int i = tid; i < 784; i += 256) {
            float4 v0 = s0[i];
            float4 v1 = s1[i];
            float4 v2 = s2[i];
            float4 v3 = s3[i];
            int h = i / 14, w = (i % 14) * 4;
            uint2* d = &fm_s[h * FS + w];
            d[0] = pack4h(v0.x, v1.x, v2.x, v3.x);
            d[1] = pack4h(v0.y, v1.y, v2.y, v3.y);
            d[2] = pack4h(v0.z, v1.z, v2.z, v3.z);
            d[3] = pack4h(v0.w, v1.w, v2.w, v3.w);
        }
    }
    __syncthreads();

    const int wid  = tid >> 5;
    const int lane = tid & 31;
    uint2* tmpw = tmp_s[wid];
    const char* tb  = (const char*)tmpw;
    const char* fmb = (const char*)fm_s;

    // stage-1 lane mapping: lanes 0..27 -> (hsub, qx)
    const int qx   = lane % 7;
    const int hsub = lane / 7;
    const bool act1 = (lane < 28);

    // stage-2 cell mapping: cell0 = lane, cell1 = lane+32
    const int p0 = lane / 7,        q0 = lane % 7;
    const int p1 = (lane + 32) / 7, q1 = (lane + 32) % 7;
    const bool has1 = (lane + 32 < 49);

    const int n = nbase + wid;

    float4 acc0 = make_float4(0.f, 0.f, 0.f, 0.f);
    float4 acc1 = make_float4(0.f, 0.f, 0.f, 0.f);

    #pragma unroll 1
    for (int j = 0; j < 9; j++) {
        const int r = b * R_PER_IMG + ((j == 0) ? n : (NN + n * 8 + (j - 1)));
        const float wroi = (j == 0) ? 1.0f : 0.125f;
        const int yinfo = __ldg(&g_yinfo[r]);
        const int ylo   = yinfo & 0xFF;
        const int span4 = yinfo >> 8;
        const int ky    = __ldg(&g_kmax[r * 2]);
        const int kx    = __ldg(&g_kmax[r * 2 + 1]);
        const int mbase = r * 16;
        const unsigned* whbase = g_wgth + (size_t)r * 168;

        // ---- stage 1: x-interp into tmp[h][q] (fp16 accum) ----
        {
            int metax = __ldg(&g_meta[mbase + 7 + qx]);
            int offx = metax & 0xFF;
            const unsigned* wpx = whbase + (7 + qx) * 12;
            #define CS1(K) case K: s1loop<K>(fmb, tmpw, ylo, span4, hsub, qx, act1, offx, wpx); break;
            switch (kx) {
                CS1(1) CS1(2) CS1(3) CS1(4) CS1(5)
                CS1(6) CS1(7) CS1(8) CS1(9)
                default: s1loop<10>(fmb, tmpw, ylo, span4, hsub, qx, act1, offx, wpx); break;
            }
            #undef CS1
        }
        __syncwarp();

        // ---- stage 2: y-interp from tmp (fp16 accum, fp32 roi combine) ----
        {
            int meta0 = __ldg(&g_meta[mbase + p0]);
            int meta1 = has1 ? __ldg(&g_meta[mbase + p1]) : meta0;
            int base0 = ((meta0 & 0xFF) - ylo) * 7 + q0;
            int base1 = ((meta1 & 0xFF) - ylo) * 7 + (has1 ? q1 : q0);
            const unsigned* wp0 = whbase + p0 * 12;
            const unsigned* wp1 = whbase + (has1 ? p1 : p0) * 12;

            float2 s001, s023, s101, s123;
            #define CS2(K) case K: { s2cell<K>(tb, base0, wp0, s001, s023); \
                                     s2cell<K>(tb, base1, wp1, s101, s123); } break;
            switch (ky) {
                CS2(1) CS2(2) CS2(3) CS2(4) CS2(5)
                CS2(6) CS2(7) CS2(8) CS2(9)
                default: { s2cell<10>(tb, base0, wp0, s001, s023);
                           s2cell<10>(tb, base1, wp1, s101, s123); } break;
            }
            #undef CS2
            acc0.x += wroi * s001.x; acc0.y += wroi * s001.y;
            acc0.z += wroi * s023.x; acc0.w += wroi * s023.y;
            acc1.x += wroi * s101.x; acc1.y += wroi * s101.y;
            acc1.z += wroi * s123.x; acc1.w += wroi * s123.y;
        }
        __syncwarp();   // tmp reuse safety before next roi
    }

    // ---- store out[b][n][c][p][q], channels c0..c0+3 ----
    float* o = out + ((size_t)(b * NN + n) * CC + c0) * (PP * PP);
    o[lane]       = acc0.x;
    o[49 + lane]  = acc0.y;
    o[98 + lane]  = acc0.z;
    o[147 + lane] = acc0.w;
    if (has1) {
        o[lane + 32]       = acc1.x;
        o[49 + lane + 32]  = acc1.y;
        o[98 + lane + 32]  = acc1.z;
        o[147 + lane + 32] = acc1.w;
    }
}

// ---------------------------------------------------------------------------
extern "C" void kernel_launch(void* const* d_in, const int* in_sizes, int n_in,
                              void* d_out, int out_size) {
    const float* fm    = (const float*)d_in[0];
    const float* boxes = (const float*)d_in[1];
    const float* gts   = (const float*)d_in[2];
    float* out = (float*)d_out;

    prep_kernel<<<(R_TOTAL * 2 + 127) / 128, 128>>>(boxes, gts);

    dim3 grid(CC / 4, BB, 8);
    roi_main_kernel<<<grid, 256>>>(fm, out);
}